// round 6
// baseline (speedup 1.0000x reference)
#include <cuda_runtime.h>
#include <cuda_bf16.h>
#include <cstdint>

// out[b,f] = -2.5*log10( sum_l A[b,l] * (trans[f,l]*w[l]) )
// wt_kernel -> g_wt bf16 [F,L];  split-K=2 bf16 mma.sync GEMM (2 CTAs/SM) -> g_part;
// reduce_log_kernel: sum halves + -2.5*log10.
// (tcgen05 unavailable: harness ptxas targets compute_103 which rejects it.)

#define BM 64
#define BN 128
#define BK 64
#define THREADS 256
#define B_ST   16384                 // BN*BK*2
#define ABF_ST 8192                  // BM*BK*2
#define OFF_ABF (3 * B_ST)           // B: 3 stages, then Abf: 2 stages
#define DYN_SMEM (OFF_ABF + 2 * ABF_ST + 1024)   // ~65KB -> 2 CTAs/SM

__device__ __align__(16) __nv_bfloat16 g_wt[128 * 8192];
__device__ __align__(16) float g_part[2 * 8192 * 128];   // split-K partials

__global__ void wt_kernel(const float* __restrict__ trans,
                          const float* __restrict__ lam, int F, int L) {
    int i4 = blockIdx.x * blockDim.x + threadIdx.x;
    int total = (F * L) >> 2;
    if (i4 >= total) return;
    int l0 = (i4 % (L >> 2)) << 2;
    float4 t = reinterpret_cast<const float4*>(trans)[i4];
    float w[4];
#pragma unroll
    for (int j = 0; j < 4; j++) {
        int l = l0 + j;
        int hi = l + 1 < L ? l + 1 : L - 1;
        int lo = l > 0 ? l - 1 : 0;
        w[j] = 0.5f * (__ldg(lam + hi) - __ldg(lam + lo));
    }
    __nv_bfloat162 p0 = __floats2bfloat162_rn(t.x * w[0], t.y * w[1]);
    __nv_bfloat162 p1 = __floats2bfloat162_rn(t.z * w[2], t.w * w[3]);
    uint2 v = { reinterpret_cast<uint32_t&>(p0), reinterpret_cast<uint32_t&>(p1) };
    reinterpret_cast<uint2*>(g_wt)[i4] = v;
}

__device__ __forceinline__ uint32_t smem_u32(const void* p) {
    uint32_t a;
    asm("{ .reg .u64 t; cvta.to.shared.u64 t, %1; cvt.u32.u64 %0, t; }"
        : "=r"(a) : "l"(p));
    return a;
}
__device__ __forceinline__ void ldmx4(uint32_t* r, uint32_t addr) {
    asm volatile("ldmatrix.sync.aligned.m8n8.x4.shared.b16 {%0,%1,%2,%3}, [%4];\n"
                 : "=r"(r[0]), "=r"(r[1]), "=r"(r[2]), "=r"(r[3]) : "r"(addr));
}
__device__ __forceinline__ void mma16816(float* c, const uint32_t* a, const uint32_t* b) {
    asm volatile("mma.sync.aligned.m16n8k16.row.col.f32.bf16.bf16.f32 "
                 "{%0,%1,%2,%3}, {%4,%5,%6,%7}, {%8,%9}, {%0,%1,%2,%3};\n"
                 : "+f"(c[0]), "+f"(c[1]), "+f"(c[2]), "+f"(c[3])
                 : "r"(a[0]), "r"(a[1]), "r"(a[2]), "r"(a[3]), "r"(b[0]), "r"(b[1]));
}
__device__ __forceinline__ uint32_t packbf2(float x, float y) {
    __nv_bfloat162 h = __floats2bfloat162_rn(x, y);
    return reinterpret_cast<uint32_t&>(h);
}
__device__ __forceinline__ void cp16(uint32_t dst, const void* src) {
    asm volatile("cp.async.cg.shared.global [%0], [%1], 16;"
                 :: "r"(dst), "l"(src) : "memory");
}
#define CP_COMMIT() asm volatile("cp.async.commit_group;" ::: "memory")
#define CP_WAIT1()  asm volatile("cp.async.wait_group 1;" ::: "memory")

__global__ void __launch_bounds__(THREADS, 2)
gemm_partial_kernel(const float* __restrict__ A, int K) {
    extern __shared__ char dynsmem[];
    const uint32_t base = (smem_u32(dynsmem) + 1023) & ~1023u;
    const uint32_t bB   = base;
    const uint32_t bAbf = base + OFF_ABF;

    const int tid  = threadIdx.x;
    const int lane = tid & 31;
    const int warp = tid >> 5;
    const size_t bm0 = (size_t)blockIdx.x * BM;
    const int kz    = blockIdx.y;
    const int Kh    = K >> 1;
    const int k0    = kz * Kh;
    const int NKT   = Kh / BK;        // 64

    // ---- A: LDG mapping. thread -> row ar = tid>>2, 16 fp32 cols at 16*(tid&3)
    const int ar = tid >> 2, ac = tid & 3;
    const float4* aSrc4 = reinterpret_cast<const float4*>(A + (bm0 + ar) * (size_t)K + k0)
                        + 4 * ac;
    const uint32_t abfrel0 = (uint32_t)ar * 128 + (uint32_t)(((2 * ac)     ^ (ar & 7)) * 16);
    const uint32_t abfrel1 = (uint32_t)ar * 128 + (uint32_t)(((2 * ac + 1) ^ (ar & 7)) * 16);

    // ---- B: cp.async mapping, 4 chunks per thread
    int brel[4];
    const __nv_bfloat16* bsrc[4];
#pragma unroll
    for (int j = 0; j < 4; j++) {
        int id = tid + 256 * j;
        int n = id >> 3, cc = id & 7;
        brel[j] = n * 128 + ((cc ^ (n & 7)) * 16);
        bsrc[j] = g_wt + (size_t)n * K + k0 + cc * 8;
    }

    // ---- mma fragment indexing (2 warps M x 4 warps N; warp tile 32x32)
    const int wmBase = (warp & 1) * 32;
    const int wnBase = (warp >> 1) * 32;
    int arow[2], brow[2];
#pragma unroll
    for (int mi = 0; mi < 2; mi++) arow[mi] = wmBase + mi * 16 + (lane & 15);
#pragma unroll
    for (int nj = 0; nj < 2; nj++) brow[nj] = wnBase + nj * 16 + ((lane >> 4) << 3) + (lane & 7);
    const int achalf = lane >> 4;
    const int bchalf = (lane >> 3) & 1;

    float acc[2][4][4];
#pragma unroll
    for (int i = 0; i < 2; i++)
#pragma unroll
        for (int j = 0; j < 4; j++)
#pragma unroll
            for (int k = 0; k < 4; k++) acc[i][j][k] = 0.f;

    float4 fa[2][4];   // A register prefetch, two tiles in flight

#define LOAD_A(T) do {                                                        \
        const float4* _p = aSrc4 + (size_t)(T) * (BK >> 2);                   \
        float4* _d = fa[(T) & 1];                                             \
        _d[0] = __ldg(_p);     _d[1] = __ldg(_p + 1);                         \
        _d[2] = __ldg(_p + 2); _d[3] = __ldg(_p + 3);                         \
    } while (0)

#define CONVERT(T) do {                                                       \
        float4* _f = fa[(T) & 1];                                             \
        const uint32_t _da = bAbf + (uint32_t)(((T) & 1) ? ABF_ST : 0);       \
        asm volatile("st.shared.v4.b32 [%0], {%1,%2,%3,%4};" ::               \
            "r"(_da + abfrel0),                                               \
            "r"(packbf2(_f[0].x, _f[0].y)), "r"(packbf2(_f[0].z, _f[0].w)),   \
            "r"(packbf2(_f[1].x, _f[1].y)), "r"(packbf2(_f[1].z, _f[1].w)) : "memory"); \
        asm volatile("st.shared.v4.b32 [%0], {%1,%2,%3,%4};" ::               \
            "r"(_da + abfrel1),                                               \
            "r"(packbf2(_f[2].x, _f[2].y)), "r"(packbf2(_f[2].z, _f[2].w)),   \
            "r"(packbf2(_f[3].x, _f[3].y)), "r"(packbf2(_f[3].z, _f[3].w)) : "memory"); \
    } while (0)

#define ISSUE_B(T, S) do {                                                    \
        const uint32_t _bd = bB + (uint32_t)(S) * B_ST;                       \
        cp16(_bd + brel[0], bsrc[0] + (size_t)(T) * BK);                      \
        cp16(_bd + brel[1], bsrc[1] + (size_t)(T) * BK);                      \
        cp16(_bd + brel[2], bsrc[2] + (size_t)(T) * BK);                      \
        cp16(_bd + brel[3], bsrc[3] + (size_t)(T) * BK);                      \
    } while (0)

    // ---------- prologue ----------
    ISSUE_B(0, 0); CP_COMMIT();
    ISSUE_B(1, 1); CP_COMMIT();
    LOAD_A(0);
    LOAD_A(1);
    CONVERT(0);
    CP_WAIT1();               // B(0) complete
    __syncthreads();

    int sCur = 0, sIss = 2;

    // ---------- main loop: one barrier per tile ----------
    for (int kt = 0; kt < NKT; kt++) {
        if (kt + 2 < NKT) {
            LOAD_A(kt + 2);           // LDG into fa[kt&1] (free: converted last iter)
            ISSUE_B(kt + 2, sIss);
        }
        CP_COMMIT();

        const uint32_t aoff = bAbf + (uint32_t)((kt & 1) ? ABF_ST : 0);
        const uint32_t boff = bB + (uint32_t)sCur * B_ST;
#pragma unroll
        for (int ks = 0; ks < 4; ks++) {
            uint32_t a[2][4], b[2][4];
#pragma unroll
            for (int mi = 0; mi < 2; mi++) {
                int c = ks * 2 + achalf;
                ldmx4(a[mi], aoff + (uint32_t)(arow[mi] * 8 + (c ^ (arow[mi] & 7))) * 16);
            }
#pragma unroll
            for (int nj = 0; nj < 2; nj++) {
                int c = ks * 2 + bchalf;
                ldmx4(b[nj], boff + (uint32_t)(brow[nj] * 8 + (c ^ (brow[nj] & 7))) * 16);
            }
#pragma unroll
            for (int mi = 0; mi < 2; mi++)
#pragma unroll
                for (int nt = 0; nt < 4; nt++)
                    mma16816(acc[mi][nt], a[mi], &b[nt >> 1][(nt & 1) * 2]);
        }

        if (kt + 1 < NKT) CONVERT(kt + 1);   // own data, no extra barrier needed
        CP_WAIT1();                          // B(kt+1) complete
        __syncthreads();                     // publish Abf[kt+1], B[kt+1]; free B[kt]

        sCur = (sCur == 2) ? 0 : sCur + 1;
        sIss = (sIss == 2) ? 0 : sIss + 1;
    }

    // ---------- store fp32 partials ----------
    float* part = g_part + (size_t)kz * (8192 * 128);
#pragma unroll
    for (int mi = 0; mi < 2; mi++) {
        const size_t row0 = bm0 + wmBase + mi * 16 + (lane >> 2);
#pragma unroll
        for (int nt = 0; nt < 4; nt++) {
            const int col = wnBase + nt * 8 + (lane & 3) * 2;
            float2 v0 = { acc[mi][nt][0], acc[mi][nt][1] };
            float2 v1 = { acc[mi][nt][2], acc[mi][nt][3] };
            *reinterpret_cast<float2*>(part + row0 * BN + col)       = v0;
            *reinterpret_cast<float2*>(part + (row0 + 8) * BN + col) = v1;
        }
    }
}

__global__ void reduce_log_kernel(float* __restrict__ out, int n4) {
    int i = blockIdx.x * blockDim.x + threadIdx.x;
    if (i >= n4) return;
    const float4* p0 = reinterpret_cast<const float4*>(g_part);
    const float4* p1 = reinterpret_cast<const float4*>(g_part + 8192 * 128);
    const float C = -0.75257498915995302f;   // -2.5 / log2(10)
    float4 a = p0[i], b = p1[i];
    float4 r;
    r.x = C * __log2f(a.x + b.x);
    r.y = C * __log2f(a.y + b.y);
    r.z = C * __log2f(a.z + b.z);
    r.w = C * __log2f(a.w + b.w);
    reinterpret_cast<float4*>(out)[i] = r;
}

extern "C" void kernel_launch(void* const* d_in, const int* in_sizes, int n_in,
                              void* d_out, int out_size) {
    const float* l_target = (const float*)d_in[0];   // [B, L] fp32
    const float* trans    = (const float*)d_in[1];   // [F, L] fp32
    const float* lam      = (const float*)d_in[2];   // [L]    fp32

    const int L = in_sizes[2];
    const int F = in_sizes[1] / L;   // 128
    const int B = in_sizes[0] / L;   // 8192
    float* out = (float*)d_out;

    cudaFuncSetAttribute(gemm_partial_kernel,
                         cudaFuncAttributeMaxDynamicSharedMemorySize, DYN_SMEM);

    int total4 = (F * L) >> 2;
    wt_kernel<<<(total4 + 255) / 256, 256>>>(trans, lam, F, L);
    dim3 grid(B / BM, 2);
    gemm_partial_kernel<<<grid, THREADS, DYN_SMEM>>>(l_target, L);
    int n4 = (B * F) / 4;
    reduce_log_kernel<<<(n4 + 255) / 256, 256>>>(out, n4);
}